// round 7
// baseline (speedup 1.0000x reference)
#include <cuda_runtime.h>
#include <cuda_fp16.h>
#include <cstdint>
#include <math.h>

// Problem sizes (fixed): B=4, S=2048, D=N=K=2048
#define BSZ 4
#define SSZ 2048
#define DSZ 2048
#define NSZ 2048
#define KSZ 2048
#define MSZ (BSZ * SSZ)   // 8192

#define NCHUNK 16
#define CLEN (SSZ / NCHUNK)  // 128

// ---------------- GEMM tiling (fp16 mma m16n8k16 + ldmatrix) ----------------
#define BM 128
#define BN 128
#define BK 64                   // halves; 64*2B = 128B per row
#define NKITER (KSZ / BK)       // 32
#define NSTAGE 3
#define SSTR_H 72               // halves per smem row (36 words -> conflict-free)
#define A_BYTES (BM * SSTR_H * 2)            // 18432
#define B_BYTES (BN * SSTR_H * 2)            // 18432
#define STAGE_BYTES (A_BYTES + B_BYTES)      // 36864
#define SMEM_BYTES (NSTAGE * STAGE_BYTES)    // 110592 (108KB)

// ---------------- scratch (device globals; no allocation allowed) ----------
__device__ float  g_buf0[(size_t)MSZ * NSZ];   // dt_lin (raw fp32)
__device__ float  g_buf1[(size_t)MSZ * NSZ];   // Bp (raw fp32)
__device__ __half g_hh[(size_t)MSZ * NSZ];     // h_all (fp16 for GEMM3)
__device__ __half g_xh[(size_t)MSZ * KSZ];     // x in fp16
__device__ __half g_wh[3 * (size_t)NSZ * KSZ]; // W_dt | W_B | W_C in fp16
__device__ float  g_prod[BSZ * NCHUNK * NSZ];
__device__ float  g_hend[BSZ * NCHUNK * NSZ];
__device__ float  g_hin[BSZ * NCHUNK * NSZ];

// ---------------- helpers ----------------
__device__ __forceinline__ float ex2(float f) {
    float r; asm("ex2.approx.f32 %0, %1;" : "=f"(r) : "f"(f)); return r;
}
__device__ __forceinline__ float lg2(float f) {
    float r; asm("lg2.approx.f32 %0, %1;" : "=f"(r) : "f"(f)); return r;
}
__device__ __forceinline__ void cp16(uint32_t s, const void* g) {
    asm volatile("cp.async.cg.shared.global [%0], [%1], 16;" :: "r"(s), "l"(g));
}
__device__ __forceinline__ void ldmx4(uint32_t* r, uint32_t addr) {
    asm volatile(
        "ldmatrix.sync.aligned.m8n8.x4.shared.b16 {%0,%1,%2,%3}, [%4];"
        : "=r"(r[0]), "=r"(r[1]), "=r"(r[2]), "=r"(r[3]) : "r"(addr));
}

// mma.sync m16n8k16 fp16 -> fp32 acc: D += A*B (A rm 16x16, B cm 16x8)
__device__ __forceinline__ void mma16(float* d, const uint32_t* a, const uint32_t* b) {
    asm volatile(
        "mma.sync.aligned.m16n8k16.row.col.f32.f16.f16.f32 "
        "{%0,%1,%2,%3}, {%4,%5,%6,%7}, {%8,%9}, {%0,%1,%2,%3};"
        : "+f"(d[0]), "+f"(d[1]), "+f"(d[2]), "+f"(d[3])
        : "r"(a[0]), "r"(a[1]), "r"(a[2]), "r"(a[3]), "r"(b[0]), "r"(b[1]));
}

// ---------------------------------------------------------------------------
// fp16 mma.sync GEMM (NT): C[m][n] = sum_k A[m][k] * W[n][k], fp32 accumulate
// CTA 128x128, 4 warps (2x2), warp tile 64x64, BK=64, 3-stage cp.async,
// ldmatrix.x4 fragment loads (8 LDSM per kk vs 32 scalar LDS).
// MODE 0: dual-output (n0 < NSZ -> C0, else C1 at n0-NSZ), raw store.
// MODE 1: single output C0 = acc + Dsk[n]*X[m][n].
// ---------------------------------------------------------------------------
template <int MODE>
__global__ __launch_bounds__(128, 2) void gemm_tc(
    const __half* __restrict__ A, const __half* __restrict__ W,
    float* __restrict__ C0, float* __restrict__ C1,
    const float* __restrict__ X, const float* __restrict__ Dsk)
{
    extern __shared__ __half smem[];
    const int tid = threadIdx.x;
    const int wid = tid >> 5, lane = tid & 31;
    const int m0 = blockIdx.y * BM;
    const int n0 = blockIdx.x * BN;
    const int wm = (wid >> 1) * 64;      // 2 m-warps
    const int wn = (wid & 1) * 64;       // 2 n-warps
    const int lr = lane >> 2;            // 0..7 (epilogue row)
    const int lc = lane & 3;             // 0..3 (epilogue col)

    const uint32_t sbase = (uint32_t)__cvta_generic_to_shared(smem);

    // ldmatrix per-lane base addresses (bytes), within stage 0.
    // A x4 tile (mt): rows wm+mt*16+(lane&15), col (lane>>4)*8
    uint32_t aAddr[4];
    #pragma unroll
    for (int mt = 0; mt < 4; mt++)
        aAddr[mt] = sbase +
            (uint32_t)(((wm + mt * 16 + (lane & 15)) * SSTR_H + ((lane >> 4) << 3)) * 2);
    // B x4 tile (ntp covers nt=2*ntp, 2*ntp+1):
    // rows wn+ntp*16+((lane>>4)<<3)+(lane&7), col ((lane>>3)&1)*8
    uint32_t bAddr[4];
    #pragma unroll
    for (int ntp = 0; ntp < 4; ntp++)
        bAddr[ntp] = sbase + (uint32_t)A_BYTES +
            (uint32_t)(((wn + ntp * 16 + ((lane >> 4) << 3) + (lane & 7)) * SSTR_H
                        + (((lane >> 3) & 1) << 3)) * 2);

    float acc[4][8][4];
    #pragma unroll
    for (int i = 0; i < 4; i++)
        #pragma unroll
        for (int j = 0; j < 8; j++) {
            acc[i][j][0] = 0.f; acc[i][j][1] = 0.f;
            acc[i][j][2] = 0.f; acc[i][j][3] = 0.f;
        }

    auto load_tile = [&](int stage, int kt) {
        const __half* Ap = A + (size_t)m0 * KSZ + kt * BK;
        const __half* Wp = W + (size_t)n0 * KSZ + kt * BK;
        uint32_t baseA = sbase + (uint32_t)(stage * STAGE_BYTES);
        uint32_t baseB = baseA + (uint32_t)A_BYTES;
        #pragma unroll
        for (int i = 0; i < 8; i++) {               // A: 128 rows x 8 x 16B
            int idx = tid + i * 128;
            int r = idx >> 3, c = idx & 7;
            cp16(baseA + (uint32_t)(r * (SSTR_H * 2) + c * 16),
                 Ap + (size_t)r * KSZ + c * 8);
        }
        #pragma unroll
        for (int i = 0; i < 8; i++) {               // B: 128 rows x 8 x 16B
            int idx = tid + i * 128;
            int r = idx >> 3, c = idx & 7;
            cp16(baseB + (uint32_t)(r * (SSTR_H * 2) + c * 16),
                 Wp + (size_t)r * KSZ + c * 8);
        }
        asm volatile("cp.async.commit_group;");
    };

    load_tile(0, 0);
    load_tile(1, 1);

    #pragma unroll 1
    for (int kt = 0; kt < NKITER; kt++) {
        const int cur = kt % NSTAGE;
        if (kt < NKITER - 1) asm volatile("cp.async.wait_group 1;");
        else                 asm volatile("cp.async.wait_group 0;");
        __syncthreads();
        // prefetch stage kt+2 (overwrites stage consumed at kt-1; safe after sync)
        if (kt + 2 < NKITER) load_tile((kt + 2) % NSTAGE, kt + 2);

        const uint32_t stOff = (uint32_t)(cur * STAGE_BYTES);
        #pragma unroll
        for (int kk = 0; kk < 4; kk++) {
            const uint32_t kbOff = stOff + kk * 32;  // 16 halves = 32B
            uint32_t af[4][4], bf[8][2];
            #pragma unroll
            for (int mt = 0; mt < 4; mt++)
                ldmx4(af[mt], aAddr[mt] + kbOff);
            #pragma unroll
            for (int ntp = 0; ntp < 4; ntp++) {
                uint32_t r[4];
                ldmx4(r, bAddr[ntp] + kbOff);
                bf[2 * ntp][0] = r[0];  bf[2 * ntp][1] = r[1];
                bf[2 * ntp + 1][0] = r[2]; bf[2 * ntp + 1][1] = r[3];
            }
            #pragma unroll
            for (int mt = 0; mt < 4; mt++)
                #pragma unroll
                for (int nt = 0; nt < 8; nt++)
                    mma16(acc[mt][nt], af[mt], bf[nt]);
        }
    }

    // epilogue
    float* Cw = C0;
    int ncol = n0;
    if (MODE == 0 && n0 >= NSZ) { Cw = C1; ncol = n0 - NSZ; }

    #pragma unroll
    for (int mt = 0; mt < 4; mt++) {
        #pragma unroll
        for (int nt = 0; nt < 8; nt++) {
            int r0 = m0 + wm + mt * 16 + lr;
            int c0 = ncol + wn + nt * 8 + lc * 2;
            float2 v0 = { acc[mt][nt][0], acc[mt][nt][1] };
            float2 v1 = { acc[mt][nt][2], acc[mt][nt][3] };
            if (MODE == 1) {
                float2 d0 = *(const float2*)(Dsk + c0);
                float2 x0 = *(const float2*)(X + (size_t)r0 * NSZ + c0);
                float2 x1 = *(const float2*)(X + (size_t)(r0 + 8) * NSZ + c0);
                v0.x += d0.x * x0.x; v0.y += d0.y * x0.y;
                v1.x += d0.x * x1.x; v1.y += d0.y * x1.y;
            }
            *(float2*)(Cw + (size_t)r0 * NSZ + c0) = v0;
            *(float2*)(Cw + (size_t)(r0 + 8) * NSZ + c0) = v1;
        }
    }
}

// ---------------------------------------------------------------------------
// Convert fp32 buffer to fp16
// ---------------------------------------------------------------------------
__global__ void tohalf_k(const float* __restrict__ in, __half* __restrict__ out)
{
    size_t i = (size_t)blockIdx.x * blockDim.x + threadIdx.x;
    float4 v = ((const float4*)in)[i];
    __half2 h0 = __floats2half2_rn(v.x, v.y);
    __half2 h1 = __floats2half2_rn(v.z, v.w);
    ((__half2*)out)[2 * i]     = h0;
    ((__half2*)out)[2 * i + 1] = h1;
}

// ---------------------------------------------------------------------------
// Fused transform: from raw dt_lin (buf0), Bp (buf1), x:
//   z = dt_lin + b_dt[n];  L = log2(1+2^(z*log2e))  (or z*log2e if large)
//   dt = L*ln2;  abar = 2^(L*Aa),  Aa = -exp(A_log[n]);  inp = dt*Bp*x
// ---------------------------------------------------------------------------
__device__ __forceinline__ void transform(float dtl, float bp, float xv,
                                          float bd, float Aa,
                                          float& abar, float& inp)
{
    float z = dtl + bd;
    float e = ex2(z * 1.442695041f);
    float L = (z > 15.0f) ? z * 1.442695041f : lg2(1.0f + e);
    abar = ex2(L * Aa);
    float dt = L * 0.69314718056f;
    inp = dt * bp * xv;
}

// ---------------------------------------------------------------------------
// Chunked selective scan (transform fused into pass1 & pass3)
// ---------------------------------------------------------------------------
__global__ void scan_pass1(const float* __restrict__ x,
                           const float* __restrict__ b_dt,
                           const float* __restrict__ A_log)
{
    int gid = blockIdx.x * blockDim.x + threadIdx.x;
    int n = gid & (NSZ - 1);
    int c = (gid >> 11) & (NCHUNK - 1);
    int b = gid >> 15;
    float bd = b_dt[n];
    float Aa = -expf(A_log[n]);
    size_t base = ((size_t)(b * SSZ + c * CLEN)) * NSZ + n;
    float h = 0.0f, p = 1.0f;
    #pragma unroll 4
    for (int t = 0; t < CLEN; t++) {
        float abar, inp;
        transform(g_buf0[base], g_buf1[base], x[base], bd, Aa, abar, inp);
        h = abar * h + inp;
        p *= abar;
        base += NSZ;
    }
    g_prod[gid] = p;
    g_hend[gid] = h;
}

__global__ void scan_pass2()
{
    int gid = blockIdx.x * blockDim.x + threadIdx.x;
    int n = gid & (NSZ - 1);
    int b = gid >> 11;
    float hin = 0.0f;
    #pragma unroll
    for (int c = 0; c < NCHUNK; c++) {
        int ci = (b * NCHUNK + c) * NSZ + n;
        g_hin[ci] = hin;
        hin = g_prod[ci] * hin + g_hend[ci];
    }
}

__global__ void scan_pass3(const float* __restrict__ x,
                           const float* __restrict__ b_dt,
                           const float* __restrict__ A_log)
{
    int gid = blockIdx.x * blockDim.x + threadIdx.x;
    int n = gid & (NSZ - 1);
    int c = (gid >> 11) & (NCHUNK - 1);
    int b = gid >> 15;
    float bd = b_dt[n];
    float Aa = -expf(A_log[n]);
    size_t base = ((size_t)(b * SSZ + c * CLEN)) * NSZ + n;
    float h = g_hin[gid];
    #pragma unroll 4
    for (int t = 0; t < CLEN; t++) {
        float abar, inp;
        transform(g_buf0[base], g_buf1[base], x[base], bd, Aa, abar, inp);
        h = abar * h + inp;
        g_hh[base] = __float2half_rn(h);     // fp16 for GEMM3 A operand
        base += NSZ;
    }
}

// ---------------------------------------------------------------------------
extern "C" void kernel_launch(void* const* d_in, const int* in_sizes, int n_in,
                              void* d_out, int out_size)
{
    const float* x      = (const float*)d_in[0];
    const float* W_dt   = (const float*)d_in[1];
    const float* b_dt   = (const float*)d_in[2];
    const float* W_B    = (const float*)d_in[3];
    const float* W_C    = (const float*)d_in[4];
    const float* A_log  = (const float*)d_in[5];
    const float* D_skip = (const float*)d_in[6];
    float* out = (float*)d_out;

    float *buf0, *buf1;
    __half *xh, *wh, *hh;
    cudaGetSymbolAddress((void**)&buf0, g_buf0);
    cudaGetSymbolAddress((void**)&buf1, g_buf1);
    cudaGetSymbolAddress((void**)&xh, g_xh);
    cudaGetSymbolAddress((void**)&wh, g_wh);
    cudaGetSymbolAddress((void**)&hh, g_hh);
    __half* wc_h = wh + 2 * (size_t)NSZ * KSZ;

    cudaFuncSetAttribute(gemm_tc<0>, cudaFuncAttributeMaxDynamicSharedMemorySize, SMEM_BYTES);
    cudaFuncSetAttribute(gemm_tc<1>, cudaFuncAttributeMaxDynamicSharedMemorySize, SMEM_BYTES);

    // fp16 conversions (W_dt and W_B land contiguously -> stacked N=4096)
    tohalf_k<<<(MSZ * (size_t)KSZ) / 4 / 256, 256>>>(x, xh);
    tohalf_k<<<(NSZ * (size_t)KSZ) / 4 / 256, 256>>>(W_dt, wh);
    tohalf_k<<<(NSZ * (size_t)KSZ) / 4 / 256, 256>>>(W_B,  wh + (size_t)NSZ * KSZ);
    tohalf_k<<<(NSZ * (size_t)KSZ) / 4 / 256, 256>>>(W_C,  wc_h);

    // dt_lin & Bp in ONE GEMM over stacked N=4096
    dim3 grid12(2 * NSZ / BN, MSZ / BM);   // (32, 64)
    gemm_tc<0><<<grid12, 128, SMEM_BYTES>>>(xh, wh, buf0, buf1, nullptr, nullptr);

    // fused transform + chunked selective scan
    scan_pass1<<<(BSZ * NCHUNK * NSZ) / 256, 256>>>(x, b_dt, A_log);
    scan_pass2<<<(BSZ * NSZ) / 256, 256>>>();
    scan_pass3<<<(BSZ * NCHUNK * NSZ) / 256, 256>>>(x, b_dt, A_log);

    // out = h @ W_C^T + D_skip * x   (skip fused in epilogue)
    dim3 grid3(NSZ / BN, MSZ / BM);        // (16, 64)
    gemm_tc<1><<<grid3, 128, SMEM_BYTES>>>(hh, wc_h, out, nullptr, x, D_skip);
}